// round 8
// baseline (speedup 1.0000x reference)
#include <cuda_runtime.h>
#include <cuda_fp16.h>
#include <stdint.h>

#define BB 8
#define TT 4096
#define NI 64
#define DD 128
#define OO 64
#define NT (BB*TT)          // 32768 rows
#define SEG 32
#define NSEG (NT/SEG)       // 1024 segments

// ------------------------- scratch (device globals) -------------------------
__device__ float g_hbar[NT*DD];
__device__ float g_z[NT*DD];
__device__ float g_seg[NSEG*DD];
__device__ uint4 g_bf1[32*32*32];   // stage1 B frags: [chunk=32(k16)][ntg=32][lane=32] {hi0,hi1,lo0,lo1}
__device__ uint4 g_bf3[64*8*32];    // stage3 B frags: [chunk=64][ntg=8][lane=32]

// ------------------------- helpers -------------------------
static __device__ __forceinline__ float clip7(float x){
  return fminf(fmaxf((x + 1.0f) * 3.5f, 0.0f), 7.0f);
}
static __device__ __forceinline__ void pack_hl(float a, float b, uint32_t& hi, uint32_t& lo){
  __half2 h = __floats2half2_rn(a, b);
  float2  f = __half22float2(h);
  __half2 l = __floats2half2_rn(a - f.x, b - f.y);
  hi = *reinterpret_cast<uint32_t*>(&h);
  lo = *reinterpret_cast<uint32_t*>(&l);
}
// stored (compressed) value pair for group grp (0: knots 0-3, 1: knots 4-7)
static __device__ __forceinline__ float2 val2(float t, int grp){
  int idx = min((int)t, 6);
  float f = t - (float)idx;
  if (grp == 0){
    if (idx <= 2)      return make_float2(1.0f - f, f);      // kept (idx, idx+1)
    else if (idx == 3) return make_float2(0.0f, 1.0f - f);   // kept (2, 3)
    else               return make_float2(0.0f, 0.0f);       // kept (0, 1)
  } else {
    if (idx <= 2)      return make_float2(0.0f, 0.0f);       // kept (0, 1)
    else if (idx == 3) return make_float2(f, 0.0f);          // kept (0, 1) -> knot4
    else               return make_float2(1.0f - f, f);      // kept (idx-4, idx-3)
  }
}
// metadata byte for one input: group0 nibble | group1 nibble << 4 (sorted 2-bit indices)
static __device__ __forceinline__ uint32_t meta8(float t){
  int idx = min((int)t, 6);
  uint32_t n0, n1;
  if (idx <= 2){ n0 = (uint32_t)idx | ((uint32_t)(idx + 1) << 2); n1 = 4u; }
  else if (idx == 3){ n0 = 2u | (3u << 2); n1 = 4u; }
  else { n0 = 4u; n1 = (uint32_t)(idx - 4) | ((uint32_t)(idx - 3) << 2); }
  return n0 | (n1 << 4);
}
static __device__ __forceinline__ void frag_hl(float t, int grp, uint32_t& hi, uint32_t& lo){
  float2 v = val2(t, grp);
  pack_hl(v.x, v.y, hi, lo);
}
static __device__ __forceinline__ float pick4(float4 v, int j){
  return j == 0 ? v.x : j == 1 ? v.y : j == 2 ? v.z : v.w;
}
static __device__ __forceinline__ void mmasp(float* c, const uint32_t* a,
                                             uint32_t b0, uint32_t b1, uint32_t b2, uint32_t b3,
                                             uint32_t e){
  asm volatile(
    "mma.sp::ordered_metadata.sync.aligned.m16n8k32.row.col.f32.f16.f16.f32 "
    "{%0,%1,%2,%3}, {%4,%5,%6,%7}, {%8,%9,%10,%11}, {%0,%1,%2,%3}, %12, 0x0;"
    : "+f"(c[0]), "+f"(c[1]), "+f"(c[2]), "+f"(c[3])
    : "r"(a[0]), "r"(a[1]), "r"(a[2]), "r"(a[3]),
      "r"(b0), "r"(b1), "r"(b2), "r"(b3), "r"(e));
}
static __device__ __forceinline__ uint32_t smem_u32(const void* p){
  uint32_t a;
  asm("{ .reg .u64 t; cvta.to.shared.u64 t, %1; cvt.u32.u64 %0, t; }" : "=r"(a) : "l"(p));
  return a;
}
static __device__ __forceinline__ void cpa16(uint32_t sa, const void* g){
  asm volatile("cp.async.cg.shared.global [%0], [%1], 16;" :: "r"(sa), "l"(g));
}
#define CPA_COMMIT()  asm volatile("cp.async.commit_group;" ::: "memory")
#define CPA_WAIT0()   asm volatile("cp.async.wait_group 0;" ::: "memory")

// ------------------------- k0: build fragment-major B tables (x16 scale) -------------------------
__global__ void k0_prep(const float* __restrict__ zv, const float* __restrict__ hv,
                        const float* __restrict__ ov){
  int t = blockIdx.x * blockDim.x + threadIdx.x;
  if (t < 32*32*32){
    int lane = t & 31, ntg = (t >> 5) & 31, K = t >> 10;
    int q = lane & 3, g = lane >> 2;
    int n  = ntg * 8 + g;
    int kr = q * 2;
    const float* tab = (n < 128) ? hv : zv;
    int nn = n & 127;
    int i0 = 2 * K;
    float v0 = tab[((i0    )*8 + kr    )*128 + nn] * 16.0f;
    float v1 = tab[((i0    )*8 + kr + 1)*128 + nn] * 16.0f;
    float v2 = tab[((i0 + 1)*8 + kr    )*128 + nn] * 16.0f;
    float v3 = tab[((i0 + 1)*8 + kr + 1)*128 + nn] * 16.0f;
    uint4 o;
    pack_hl(v0, v1, o.x, o.z);
    pack_hl(v2, v3, o.y, o.w);
    g_bf1[t] = o;
  } else if (t < 32*32*32 + 64*8*32){
    int e = t - 32*32*32;
    int lane = e & 31, ntg = (e >> 5) & 7, K = e >> 8;
    int q = lane & 3, g = lane >> 2;
    int n  = ntg * 8 + g;
    int kr = q * 2;
    int i0 = 2 * K;
    float v0 = ov[((i0    )*8 + kr    )*64 + n] * 16.0f;
    float v1 = ov[((i0    )*8 + kr + 1)*64 + n] * 16.0f;
    float v2 = ov[((i0 + 1)*8 + kr    )*64 + n] * 16.0f;
    float v3 = ov[((i0 + 1)*8 + kr + 1)*64 + n] * 16.0f;
    uint4 o;
    pack_hl(v0, v1, o.x, o.z);
    pack_hl(v2, v3, o.y, o.w);
    g_bf3[e] = o;
  }
}

// ------------------------- K1: stage-1 sparse HMMA GEMM (h_bar 3-pass + z 1-pass) -------------------------
// CTA: 128 thr = 4 warps; warp (mr, nc): mr -> 32 rows; each warp: 64 h-cols (3-pass) + 64 z-cols (1-pass).
// k32 super-steps: 16. smem: t_s 64x68 f32 (17408B, 16B-aligned rows) + B ring 2 x 32KB = 82944B.
#define SW1 68
__global__ void __launch_bounds__(128) k1_mma(const float* __restrict__ x){
  extern __shared__ char smraw[];
  float* t_s = (float*)smraw;
  uint4* bbuf = (uint4*)(smraw + 64 * SW1 * 4);
  const uint32_t bbase = smem_u32(bbuf);

  const int tid = threadIdx.x;
  const int n0  = blockIdx.x * 64;

  // prologue: issue super-step 0 (chunks 0,1 = 2048 uint4) into slot 0
  {
    uint32_t sa = bbase + (uint32_t)tid * 16u;
    const uint4* gs = g_bf1 + tid;
    #pragma unroll
    for (int j = 0; j < 16; ++j) cpa16(sa + j * 128 * 16, gs + j * 128);
    CPA_COMMIT();
  }

  // prepass: clipped grid coords for the 64x64 x-tile
  #pragma unroll
  for (int e = tid; e < 64 * 16; e += 128){
    int r = e >> 4, c4 = e & 15;
    float4 v = ((const float4*)(x + (size_t)(n0 + r) * NI))[c4];
    float* d = &t_s[r * SW1 + c4 * 4];
    d[0] = clip7(v.x); d[1] = clip7(v.y); d[2] = clip7(v.z); d[3] = clip7(v.w);
  }
  __syncthreads();

  const int w = tid >> 5, lane = tid & 31;
  const int mr = w & 1, nc = w >> 1;
  const int rowbase = mr * 32;
  const int q = lane & 3, g = lane >> 2;
  const int grp = q & 1, ja = q >> 1;
  const int h2 = (lane & 1) * 2;     // metadata k-half: inputs h2, h2+1 of this super-step

  // acc[mt][nt]: nt 0-7 = h cols (nc*64+nt*8), nt 8-15 = z cols (128 + nc*64 + nt*8)
  float acc[2][16][4];
  #pragma unroll
  for (int a = 0; a < 2; ++a)
    #pragma unroll
    for (int b = 0; b < 16; ++b)
      #pragma unroll
      for (int c = 0; c < 4; ++c) acc[a][b][c] = 0.0f;

  #pragma unroll 1
  for (int S = 0; S < 16; ++S){
    // A fragments + metadata (overlaps in-flight copy of step S)
    const int colf = S * 4;
    uint32_t ah[2][4], al[2][4], em[2];
    #pragma unroll
    for (int mt = 0; mt < 2; ++mt){
      int r0 = rowbase + mt * 16 + g;
      float4 tA = *(const float4*)&t_s[ r0      * SW1 + colf];
      float4 tB = *(const float4*)&t_s[(r0 + 8) * SW1 + colf];
      frag_hl(pick4(tA, ja),     grp, ah[mt][0], al[mt][0]);
      frag_hl(pick4(tB, ja),     grp, ah[mt][1], al[mt][1]);
      frag_hl(pick4(tA, ja + 2), grp, ah[mt][2], al[mt][2]);
      frag_hl(pick4(tB, ja + 2), grp, ah[mt][3], al[mt][3]);
      // metadata: thread pair covers k-halves; this thread = k-half h2 for rows g and g+8
      em[mt] = meta8(pick4(tA, h2)) | (meta8(pick4(tA, h2 + 1)) << 8)
             | (meta8(pick4(tB, h2)) << 16) | (meta8(pick4(tB, h2 + 1)) << 24);
    }

    CPA_WAIT0();          // step S landed
    __syncthreads();      // all warps past step S-1 MMAs -> other slot reusable

    if (S + 1 < 16){      // issue S+1 into the other slot; overlaps MMAs below
      uint32_t sa = bbase + (uint32_t)(((S + 1) & 1) * 2048 + tid) * 16u;
      const uint4* gs = g_bf1 + (size_t)(S + 1) * 2048 + tid;
      #pragma unroll
      for (int j = 0; j < 16; ++j) cpa16(sa + j * 128 * 16, gs + j * 128);
      CPA_COMMIT();
    }

    const uint4* slot = bbuf + (S & 1) * 2048;
    #pragma unroll
    for (int nt = 0; nt < 8; ++nt){
      const uint4* ph = slot + (nc * 8 + nt) * 32 + lane;          // h cols
      uint4 b0 = ph[0];            // chunk 2S   (k 0-15)
      uint4 b1 = ph[1024];         // chunk 2S+1 (k 16-31)
      #pragma unroll
      for (int mt = 0; mt < 2; ++mt){
        mmasp(acc[mt][nt], ah[mt], b0.x, b0.y, b1.x, b1.y, em[mt]);  // Ah*Bh
        mmasp(acc[mt][nt], ah[mt], b0.z, b0.w, b1.z, b1.w, em[mt]);  // Ah*Bl
        mmasp(acc[mt][nt], al[mt], b0.x, b0.y, b1.x, b1.y, em[mt]);  // Al*Bh
      }
      const uint4* pz = slot + (16 + nc * 8 + nt) * 32 + lane;     // z cols
      uint2 z0 = *(const uint2*)&pz[0];
      uint2 z1 = *(const uint2*)&pz[1024];
      #pragma unroll
      for (int mt = 0; mt < 2; ++mt)
        mmasp(acc[mt][nt + 8], ah[mt], z0.x, z0.y, z1.x, z1.y, em[mt]);  // z: Ah*Bh
    }
  }

  // epilogue: scale 1/16; h -> g_hbar + segment sums; z -> sigmoid -> g_z
  const float sc = 0.0625f;
  const int sgi = blockIdx.x * 2 + mr;
  #pragma unroll
  for (int nt = 0; nt < 8; ++nt){
    const int col = nc * 64 + nt * 8 + q * 2;
    float s0 = 0.0f, s1 = 0.0f;
    #pragma unroll
    for (int mt = 0; mt < 2; ++mt){
      float c0 = acc[mt][nt][0] * sc, c1 = acc[mt][nt][1] * sc;
      float c2 = acc[mt][nt][2] * sc, c3 = acc[mt][nt][3] * sc;
      int rg = n0 + rowbase + mt * 16 + g;
      *(float2*)&g_hbar[(size_t) rg      * DD + col] = make_float2(c0, c1);
      *(float2*)&g_hbar[(size_t)(rg + 8) * DD + col] = make_float2(c2, c3);
      s0 += c0 + c2; s1 += c1 + c3;
      float z0 = acc[mt][nt + 8][0] * sc, z1 = acc[mt][nt + 8][1] * sc;
      float z2 = acc[mt][nt + 8][2] * sc, z3 = acc[mt][nt + 8][3] * sc;
      z0 = 1.0f / (1.0f + __expf(-z0)); z1 = 1.0f / (1.0f + __expf(-z1));
      z2 = 1.0f / (1.0f + __expf(-z2)); z3 = 1.0f / (1.0f + __expf(-z3));
      *(float2*)&g_z[(size_t) rg      * DD + col] = make_float2(z0, z1);
      *(float2*)&g_z[(size_t)(rg + 8) * DD + col] = make_float2(z2, z3);
    }
    #pragma unroll
    for (int off = 4; off < 32; off <<= 1){
      s0 += __shfl_xor_sync(0xFFFFFFFFu, s0, off);
      s1 += __shfl_xor_sync(0xFFFFFFFFu, s1, off);
    }
    if (g == 0)
      *(float2*)&g_seg[(size_t)sgi * DD + col] = make_float2(s0, s1);
  }
}

// ------------------------- k2b: exclusive scan over segments (per batch) -------------------------
__global__ void k2b_scan(const float* __restrict__ h0){
  int b = blockIdx.x, d = threadIdx.x;
  float run = h0[b * DD + d];
  float* p = g_seg + (size_t)b * (TT / SEG) * DD + d;
  #pragma unroll 1
  for (int gq = 0; gq < (TT / SEG) / 8; ++gq){
    float v[8];
    #pragma unroll
    for (int j = 0; j < 8; ++j) v[j] = p[(gq * 8 + j) * DD];
    #pragma unroll
    for (int j = 0; j < 8; ++j){ float t = v[j]; p[(gq * 8 + j) * DD] = run; run += t; }
  }
}

// ------------------------- k2c: ht = c + z*(h_bar - c) -------------------------
__global__ void __launch_bounds__(128) k2c_ht(float* __restrict__ out_ht){
  int si = blockIdx.x, d = threadIdx.x;
  float c = g_seg[(size_t)si * DD + d];
  size_t base = (size_t)si * SEG * DD + d;
  #pragma unroll
  for (int t0 = 0; t0 < SEG; t0 += 8){
    float hb[8], zz[8];
    #pragma unroll
    for (int j = 0; j < 8; ++j){
      hb[j] = g_hbar[base + (size_t)(t0 + j) * DD];
      zz[j] = g_z  [base + (size_t)(t0 + j) * DD];
    }
    #pragma unroll
    for (int j = 0; j < 8; ++j){
      c += hb[j];
      out_ht[base + (size_t)(t0 + j) * DD] = fmaf(zz[j], hb[j] - c, c);
    }
  }
}

// ------------------------- K3: stage-3 sparse HMMA GEMM (y), 2-pass -------------------------
// CTA: 128 thr = 4 warps; warp mr -> 32 rows, all 64 cols. M/CTA=128 -> grid 256.
// k32 super-steps: 32. smem: t3_s 128x132 f32 (67584B, 16B-aligned rows) + B ring 2 x 8KB = 83968B.
#define SW3 132
__global__ void __launch_bounds__(128) k3_mma(const float* __restrict__ ht,
                                              float* __restrict__ y){
  extern __shared__ char smraw[];
  float* t3_s = (float*)smraw;
  uint4* bbuf = (uint4*)(smraw + 128 * SW3 * 4);
  const uint32_t bbase = smem_u32(bbuf);

  const int tid = threadIdx.x;
  const int n0  = blockIdx.x * 128;

  {
    uint32_t sa = bbase + (uint32_t)tid * 16u;
    const uint4* gs = g_bf3 + tid;
    #pragma unroll
    for (int j = 0; j < 4; ++j) cpa16(sa + j * 128 * 16, gs + j * 128);
    CPA_COMMIT();
  }

  #pragma unroll 1
  for (int e = tid; e < 128 * 32; e += 128){
    int r = e >> 5, c4 = e & 31;
    float4 v = ((const float4*)(ht + (size_t)(n0 + r) * DD))[c4];
    float* d = &t3_s[r * SW3 + c4 * 4];
    d[0] = clip7(v.x); d[1] = clip7(v.y); d[2] = clip7(v.z); d[3] = clip7(v.w);
  }
  __syncthreads();

  const int mr = tid >> 5, lane = tid & 31;
  const int rowbase = mr * 32;
  const int q = lane & 3, g = lane >> 2;
  const int grp = q & 1, ja = q >> 1;
  const int h2 = (lane & 1) * 2;

  float acc[2][8][4];
  #pragma unroll
  for (int a = 0; a < 2; ++a)
    #pragma unroll
    for (int b = 0; b < 8; ++b)
      #pragma unroll
      for (int c = 0; c < 4; ++c) acc[a][b][c] = 0.0f;

  #pragma unroll 1
  for (int S = 0; S < 32; ++S){
    const int colf = S * 4;
    uint32_t ah[2][4], al[2][4], em[2];
    #pragma unroll
    for (int mt = 0; mt < 2; ++mt){
      int r0 = rowbase + mt * 16 + g;
      float4 tA = *(const float4*)&t3_s[ r0      * SW3 + colf];
      float4 tB = *(const float4*)&t3_s[(r0 + 8) * SW3 + colf];
      frag_hl(pick4(tA, ja),     grp, ah[mt][0], al[mt][0]);
      frag_hl(pick4(tB, ja),     grp, ah[mt][1], al[mt][1]);
      frag_hl(pick4(tA, ja + 2), grp, ah[mt][2], al[mt][2]);
      frag_hl(pick4(tB, ja + 2), grp, ah[mt][3], al[mt][3]);
      em[mt] = meta8(pick4(tA, h2)) | (meta8(pick4(tA, h2 + 1)) << 8)
             | (meta8(pick4(tB, h2)) << 16) | (meta8(pick4(tB, h2 + 1)) << 24);
    }

    CPA_WAIT0();
    __syncthreads();

    if (S + 1 < 32){
      uint32_t sa = bbase + (uint32_t)(((S + 1) & 1) * 512 + tid) * 16u;
      const uint4* gs = g_bf3 + (size_t)(S + 1) * 512 + tid;
      #pragma unroll
      for (int j = 0; j < 4; ++j) cpa16(sa + j * 128 * 16, gs + j * 128);
      CPA_COMMIT();
    }

    const uint4* slot = bbuf + (S & 1) * 512;
    #pragma unroll
    for (int nt = 0; nt < 8; ++nt){
      const uint4* ph = slot + nt * 32 + lane;
      uint4 b0 = ph[0];
      uint4 b1 = ph[256];
      #pragma unroll
      for (int mt = 0; mt < 2; ++mt){
        mmasp(acc[mt][nt], ah[mt], b0.x, b0.y, b1.x, b1.y, em[mt]);  // Ah*Bh
        mmasp(acc[mt][nt], al[mt], b0.x, b0.y, b1.x, b1.y, em[mt]);  // Al*Bh
      }
    }
  }

  const float sc = 0.0625f;
  #pragma unroll
  for (int nt = 0; nt < 8; ++nt){
    const int col = nt * 8 + q * 2;
    #pragma unroll
    for (int mt = 0; mt < 2; ++mt){
      int rg = n0 + rowbase + mt * 16 + g;
      *(float2*)&y[(size_t) rg      * OO + col] =
          make_float2(acc[mt][nt][0] * sc, acc[mt][nt][1] * sc);
      *(float2*)&y[(size_t)(rg + 8) * OO + col] =
          make_float2(acc[mt][nt][2] * sc, acc[mt][nt][3] * sc);
    }
  }
}

// ------------------------- host -------------------------
extern "C" void kernel_launch(void* const* d_in, const int* in_sizes, int n_in,
                              void* d_out, int out_size) {
  const float* x  = (const float*)d_in[0];   // (B,T,I)
  const float* h0 = (const float*)d_in[1];   // (B,D)
  const float* zv = (const float*)d_in[2];   // (I,P,D)
  const float* hv = (const float*)d_in[3];   // (I,P,D)
  const float* ov = (const float*)d_in[4];   // (D,P,O)

  float* y  = (float*)d_out;                     // (B,T,O)
  float* ht = (float*)d_out + (size_t)NT * OO;   // (B,T,D)

  const int smem1 = 64 * SW1 * 4 + 2 * 32768;    // 82944
  const int smem3 = 128 * SW3 * 4 + 2 * 8192;    // 83968
  cudaFuncSetAttribute(k1_mma, cudaFuncAttributeMaxDynamicSharedMemorySize, smem1);
  cudaFuncSetAttribute(k3_mma, cudaFuncAttributeMaxDynamicSharedMemorySize, smem3);

  k0_prep<<<(32*32*32 + 64*8*32 + 255) / 256, 256>>>(zv, hv, ov);
  k1_mma<<<512, 128, smem1>>>(x);
  k2b_scan<<<BB, DD>>>(h0);
  k2c_ht<<<NSEG, DD>>>(ht);
  k3_mma<<<256, 128, smem3>>>(ht, y);
}

// round 9
// speedup vs baseline: 1.5212x; 1.5212x over previous
#include <cuda_runtime.h>
#include <cuda_fp16.h>
#include <stdint.h>

#define BB 8
#define TT 4096
#define NI 64
#define DD 128
#define OO 64
#define NT (BB*TT)          // 32768 rows
#define SEG 32
#define NSEG (NT/SEG)       // 1024 segments

// ------------------------- scratch (device globals) -------------------------
__device__ float g_hbar[NT*DD];
__device__ float g_z[NT*DD];
__device__ float g_seg[NSEG*DD];
__device__ uint4 g_bf1[32*32*32];   // stage1 B frags: [K=32][ntg=32][lane=32] {hi0,hi1,lo0,lo1}
__device__ uint4 g_bf3[64*8*32];    // stage3 B frags: [K=64][ntg=8][lane=32]

// ------------------------- helpers -------------------------
static __device__ __forceinline__ float clip7(float x){
  return fminf(fmaxf((x + 1.0f) * 3.5f, 0.0f), 7.0f);
}
static __device__ __forceinline__ float hatf(float t, float p){
  return fmaxf(0.0f, 1.0f - fabsf(t - p));
}
static __device__ __forceinline__ void pack_hl(float a, float b, uint32_t& hi, uint32_t& lo){
  __half2 h = __floats2half2_rn(a, b);
  float2  f = __half22float2(h);
  __half2 l = __floats2half2_rn(a - f.x, b - f.y);
  hi = *reinterpret_cast<uint32_t*>(&h);
  lo = *reinterpret_cast<uint32_t*>(&l);
}
static __device__ __forceinline__ void mma16816(float* c, const uint32_t* a, uint32_t b0, uint32_t b1){
  asm volatile(
    "mma.sync.aligned.m16n8k16.row.col.f32.f16.f16.f32 "
    "{%0,%1,%2,%3}, {%4,%5,%6,%7}, {%8,%9}, {%0,%1,%2,%3};"
    : "+f"(c[0]), "+f"(c[1]), "+f"(c[2]), "+f"(c[3])
    : "r"(a[0]), "r"(a[1]), "r"(a[2]), "r"(a[3]), "r"(b0), "r"(b1));
}
static __device__ __forceinline__ uint32_t smem_u32(const void* p){
  uint32_t a;
  asm("{ .reg .u64 t; cvta.to.shared.u64 t, %1; cvt.u32.u64 %0, t; }" : "=r"(a) : "l"(p));
  return a;
}
static __device__ __forceinline__ void cpa16(uint32_t sa, const void* g){
  asm volatile("cp.async.cg.shared.global [%0], [%1], 16;" :: "r"(sa), "l"(g));
}
#define CPA_COMMIT()  asm volatile("cp.async.commit_group;" ::: "memory")
#define CPA_WAIT1()   asm volatile("cp.async.wait_group 1;" ::: "memory")

// ------------------------- k0: build fragment-major B tables (x16 scale) -------------------------
__global__ void k0_prep(const float* __restrict__ zv, const float* __restrict__ hv,
                        const float* __restrict__ ov){
  int t = blockIdx.x * blockDim.x + threadIdx.x;
  if (t < 32*32*32){
    int lane = t & 31, ntg = (t >> 5) & 31, K = t >> 10;
    int q = lane & 3, g = lane >> 2;
    int n  = ntg * 8 + g;
    int kr = q * 2;
    const float* tab = (n < 128) ? hv : zv;
    int nn = n & 127;
    int i0 = 2 * K;
    float v0 = tab[((i0    )*8 + kr    )*128 + nn] * 16.0f;
    float v1 = tab[((i0    )*8 + kr + 1)*128 + nn] * 16.0f;
    float v2 = tab[((i0 + 1)*8 + kr    )*128 + nn] * 16.0f;
    float v3 = tab[((i0 + 1)*8 + kr + 1)*128 + nn] * 16.0f;
    uint4 o;
    pack_hl(v0, v1, o.x, o.z);
    pack_hl(v2, v3, o.y, o.w);
    g_bf1[t] = o;
  } else if (t < 32*32*32 + 64*8*32){
    int e = t - 32*32*32;
    int lane = e & 31, ntg = (e >> 5) & 7, K = e >> 8;
    int q = lane & 3, g = lane >> 2;
    int n  = ntg * 8 + g;
    int kr = q * 2;
    int i0 = 2 * K;
    float v0 = ov[((i0    )*8 + kr    )*64 + n] * 16.0f;
    float v1 = ov[((i0    )*8 + kr + 1)*64 + n] * 16.0f;
    float v2 = ov[((i0 + 1)*8 + kr    )*64 + n] * 16.0f;
    float v3 = ov[((i0 + 1)*8 + kr + 1)*64 + n] * 16.0f;
    uint4 o;
    pack_hl(v0, v1, o.x, o.z);
    pack_hl(v2, v3, o.y, o.w);
    g_bf3[e] = o;
  }
}

// ------------------------- K1: stage-1 HMMA GEMM (h_bar 3-pass + z 1-pass) -------------------------
// CTA: 128 thr = 4 warps; warp (mr, nc): mr -> 32 rows; each warp: 64 h-cols (3-pass) + 64 z-cols (1-pass).
// M/CTA=64 -> grid 512. smem: t_s 64x66 f32 (16896B) + B ring 3 x 16KB = 66048B.
#define SW1 66
__global__ void __launch_bounds__(128) k1_mma(const float* __restrict__ x){
  extern __shared__ char smraw[];
  float* t_s = (float*)smraw;
  uint4* bbuf = (uint4*)(smraw + 64 * SW1 * 4);
  const uint32_t bbase = smem_u32(bbuf);

  const int tid = threadIdx.x;
  const int n0  = blockIdx.x * 64;

  // prologue: start copies for K=0,1 immediately (overlap with prepass)
  #pragma unroll
  for (int s = 0; s < 2; ++s){
    uint32_t sa = bbase + (uint32_t)(s * 1024 + tid) * 16u;
    const uint4* gs = g_bf1 + (size_t)s * 1024 + tid;
    #pragma unroll
    for (int j = 0; j < 8; ++j) cpa16(sa + j * 128 * 16, gs + j * 128);
    CPA_COMMIT();
  }

  // prepass: t = clipped grid coords for the 64x64 x-tile
  #pragma unroll
  for (int e = tid; e < 64 * 16; e += 128){
    int r = e >> 4, c4 = e & 15;
    float4 v = ((const float4*)(x + (size_t)(n0 + r) * NI))[c4];
    float* d = &t_s[r * SW1 + c4 * 4];
    d[0] = clip7(v.x); d[1] = clip7(v.y); d[2] = clip7(v.z); d[3] = clip7(v.w);
  }
  __syncthreads();

  const int w = tid >> 5, lane = tid & 31;
  const int mr = w & 1, nc = w >> 1;
  const int rowbase = mr * 32;
  const int q = lane & 3, g = lane >> 2;
  const float p0 = (float)(2 * q);

  // acc[mt][nt][*]: nt 0-7 = h cols (nc*64 + nt*8), nt 8-15 = z cols
  float acc[2][16][4];
  #pragma unroll
  for (int a = 0; a < 2; ++a)
    #pragma unroll
    for (int b = 0; b < 16; ++b)
      #pragma unroll
      for (int c = 0; c < 4; ++c) acc[a][b][c] = 0.0f;

  #pragma unroll 1
  for (int K = 0; K < 32; ++K){
    const int i0 = 2 * K;
    uint32_t ah[2][4], al[2][4];
    #pragma unroll
    for (int mt = 0; mt < 2; ++mt){
      int r0 = rowbase + mt * 16 + g;
      float2 tA = *(const float2*)&t_s[ r0      * SW1 + i0];
      float2 tB = *(const float2*)&t_s[(r0 + 8) * SW1 + i0];
      pack_hl(hatf(tA.x, p0), hatf(tA.x, p0 + 1.0f), ah[mt][0], al[mt][0]);
      pack_hl(hatf(tB.x, p0), hatf(tB.x, p0 + 1.0f), ah[mt][1], al[mt][1]);
      pack_hl(hatf(tA.y, p0), hatf(tA.y, p0 + 1.0f), ah[mt][2], al[mt][2]);
      pack_hl(hatf(tB.y, p0), hatf(tB.y, p0 + 1.0f), ah[mt][3], al[mt][3]);
    }

    CPA_WAIT1();
    __syncthreads();

    if (K + 2 < 32){
      int s = (K + 2) % 3;
      uint32_t sa = bbase + (uint32_t)(s * 1024 + tid) * 16u;
      const uint4* gs = g_bf1 + (size_t)(K + 2) * 1024 + tid;
      #pragma unroll
      for (int j = 0; j < 8; ++j) cpa16(sa + j * 128 * 16, gs + j * 128);
      CPA_COMMIT();
    }

    const uint4* bsh = bbuf + (K % 3) * 1024 + (nc * 8) * 32 + lane;
    const uint4* bsz = bbuf + (K % 3) * 1024 + (16 + nc * 8) * 32 + lane;
    #pragma unroll
    for (int nt = 0; nt < 8; ++nt){
      uint4 bv = bsh[nt * 32];
      #pragma unroll
      for (int mt = 0; mt < 2; ++mt){
        mma16816(acc[mt][nt], ah[mt], bv.x, bv.y);   // Ah*Bh
        mma16816(acc[mt][nt], ah[mt], bv.z, bv.w);   // Ah*Bl
        mma16816(acc[mt][nt], al[mt], bv.x, bv.y);   // Al*Bh
      }
      uint2 bz = *(const uint2*)&bsz[nt * 32];
      #pragma unroll
      for (int mt = 0; mt < 2; ++mt)
        mma16816(acc[mt][nt + 8], ah[mt], bz.x, bz.y);  // z: Ah*Bh only
    }
  }

  // epilogue
  const float sc = 0.0625f;
  const int sgi = blockIdx.x * 2 + mr;
  #pragma unroll
  for (int nt = 0; nt < 8; ++nt){
    const int col = nc * 64 + nt * 8 + q * 2;
    float s0 = 0.0f, s1 = 0.0f;
    #pragma unroll
    for (int mt = 0; mt < 2; ++mt){
      float c0 = acc[mt][nt][0] * sc, c1 = acc[mt][nt][1] * sc;
      float c2 = acc[mt][nt][2] * sc, c3 = acc[mt][nt][3] * sc;
      int rg = n0 + rowbase + mt * 16 + g;
      *(float2*)&g_hbar[(size_t) rg      * DD + col] = make_float2(c0, c1);
      *(float2*)&g_hbar[(size_t)(rg + 8) * DD + col] = make_float2(c2, c3);
      s0 += c0 + c2; s1 += c1 + c3;
      float z0 = acc[mt][nt + 8][0] * sc, z1 = acc[mt][nt + 8][1] * sc;
      float z2 = acc[mt][nt + 8][2] * sc, z3 = acc[mt][nt + 8][3] * sc;
      z0 = 1.0f / (1.0f + __expf(-z0)); z1 = 1.0f / (1.0f + __expf(-z1));
      z2 = 1.0f / (1.0f + __expf(-z2)); z3 = 1.0f / (1.0f + __expf(-z3));
      *(float2*)&g_z[(size_t) rg      * DD + col] = make_float2(z0, z1);
      *(float2*)&g_z[(size_t)(rg + 8) * DD + col] = make_float2(z2, z3);
    }
    #pragma unroll
    for (int off = 4; off < 32; off <<= 1){
      s0 += __shfl_xor_sync(0xFFFFFFFFu, s0, off);
      s1 += __shfl_xor_sync(0xFFFFFFFFu, s1, off);
    }
    if (g == 0)
      *(float2*)&g_seg[(size_t)sgi * DD + col] = make_float2(s0, s1);
  }
}

// ------------------------- k2b: exclusive scan over segments (per batch) -------------------------
__global__ void k2b_scan(const float* __restrict__ h0){
  int b = blockIdx.x, d = threadIdx.x;
  float run = h0[b * DD + d];
  float* p = g_seg + (size_t)b * (TT / SEG) * DD + d;
  #pragma unroll 1
  for (int gq = 0; gq < (TT / SEG) / 16; ++gq){
    float v[16];
    #pragma unroll
    for (int j = 0; j < 16; ++j) v[j] = p[(gq * 16 + j) * DD];
    #pragma unroll
    for (int j = 0; j < 16; ++j){ float t = v[j]; p[(gq * 16 + j) * DD] = run; run += t; }
  }
}

// ------------------------- K3: fused scan-combine + stage-3 HMMA GEMM (y), 2-pass -------------------------
// Prepass computes ht = c + z*(h_bar - c) inline (tile = 4 scan segments), writes ht to gmem
// and clip7(ht) into t3_s. CTA: 128 thr = 4 warps; warp mr -> 32 rows, all 64 cols. grid 256.
// smem: t3_s 128x130 f32 (66560B) + B ring 3 x 4KB = 78848B.
#define SW3 130
__global__ void __launch_bounds__(128) k3_mma(float* __restrict__ out_ht,
                                              float* __restrict__ y){
  extern __shared__ char smraw[];
  float* t3_s = (float*)smraw;
  uint4* bbuf = (uint4*)(smraw + 128 * SW3 * 4);
  const uint32_t bbase = smem_u32(bbuf);

  const int tid = threadIdx.x;
  const int n0  = blockIdx.x * 128;

  // GEMM prologue copies overlap the fused scan prepass below
  #pragma unroll
  for (int s = 0; s < 2; ++s){
    uint32_t sa = bbase + (uint32_t)(s * 256 + tid) * 16u;
    const uint4* gs = g_bf3 + (size_t)s * 256 + tid;
    #pragma unroll
    for (int j = 0; j < 2; ++j) cpa16(sa + j * 128 * 16, gs + j * 128);
    CPA_COMMIT();
  }

  // fused prepass: per-channel segment cumsum + combine (replaces k2c)
  {
    const int d = tid;                     // channel 0..127
    #pragma unroll 1
    for (int s4 = 0; s4 < 4; ++s4){
      const int seg = blockIdx.x * 4 + s4;
      float c = g_seg[(size_t)seg * DD + d];
      const size_t base = ((size_t)n0 + s4 * 32) * DD + d;
      #pragma unroll 1
      for (int t0 = 0; t0 < 32; t0 += 8){
        float hb[8], zz[8];
        #pragma unroll
        for (int j = 0; j < 8; ++j){
          hb[j] = g_hbar[base + (size_t)(t0 + j) * DD];
          zz[j] = g_z  [base + (size_t)(t0 + j) * DD];
        }
        #pragma unroll
        for (int j = 0; j < 8; ++j){
          c += hb[j];
          float hv = fmaf(zz[j], hb[j] - c, c);
          out_ht[base + (size_t)(t0 + j) * DD] = hv;
          t3_s[(s4 * 32 + t0 + j) * SW3 + d] = clip7(hv);
        }
      }
    }
  }
  __syncthreads();

  const int mr = tid >> 5, lane = tid & 31;
  const int rowbase = mr * 32;
  const int q = lane & 3, g = lane >> 2;
  const float p0 = (float)(2 * q);

  float acc[2][8][4];
  #pragma unroll
  for (int a = 0; a < 2; ++a)
    #pragma unroll
    for (int b = 0; b < 8; ++b)
      #pragma unroll
      for (int c = 0; c < 4; ++c) acc[a][b][c] = 0.0f;

  #pragma unroll 1
  for (int K = 0; K < 64; ++K){
    const int i0 = 2 * K;
    uint32_t ah[2][4], al[2][4];
    #pragma unroll
    for (int mt = 0; mt < 2; ++mt){
      int r0 = rowbase + mt * 16 + g;
      float2 tA = *(const float2*)&t3_s[ r0      * SW3 + i0];
      float2 tB = *(const float2*)&t3_s[(r0 + 8) * SW3 + i0];
      pack_hl(hatf(tA.x, p0), hatf(tA.x, p0 + 1.0f), ah[mt][0], al[mt][0]);
      pack_hl(hatf(tB.x, p0), hatf(tB.x, p0 + 1.0f), ah[mt][1], al[mt][1]);
      pack_hl(hatf(tA.y, p0), hatf(tA.y, p0 + 1.0f), ah[mt][2], al[mt][2]);
      pack_hl(hatf(tB.y, p0), hatf(tB.y, p0 + 1.0f), ah[mt][3], al[mt][3]);
    }

    CPA_WAIT1();
    __syncthreads();

    if (K + 2 < 64){
      int s = (K + 2) % 3;
      uint32_t sa = bbase + (uint32_t)(s * 256 + tid) * 16u;
      const uint4* gs = g_bf3 + (size_t)(K + 2) * 256 + tid;
      #pragma unroll
      for (int j = 0; j < 2; ++j) cpa16(sa + j * 128 * 16, gs + j * 128);
      CPA_COMMIT();
    }

    const uint4* bs = bbuf + (K % 3) * 256 + lane;
    uint4 bv = bs[0];
    #pragma unroll
    for (int nt = 0; nt < 8; ++nt){
      uint4 nb;
      if (nt < 7) nb = bs[(nt + 1) * 32];
      #pragma unroll
      for (int mt = 0; mt < 2; ++mt){
        mma16816(acc[mt][nt], ah[mt], bv.x, bv.y);   // Ah*Bh
        mma16816(acc[mt][nt], al[mt], bv.x, bv.y);   // Al*Bh
      }
      if (nt < 7) bv = nb;
    }
  }

  const float sc = 0.0625f;
  #pragma unroll
  for (int nt = 0; nt < 8; ++nt){
    const int col = nt * 8 + q * 2;
    #pragma unroll
    for (int mt = 0; mt < 2; ++mt){
      int rg = n0 + rowbase + mt * 16 + g;
      *(float2*)&y[(size_t) rg      * OO + col] =
          make_float2(acc[mt][nt][0] * sc, acc[mt][nt][1] * sc);
      *(float2*)&y[(size_t)(rg + 8) * OO + col] =
          make_float2(acc[mt][nt][2] * sc, acc[mt][nt][3] * sc);
    }
  }
}

// ------------------------- host -------------------------
extern "C" void kernel_launch(void* const* d_in, const int* in_sizes, int n_in,
                              void* d_out, int out_size) {
  const float* x  = (const float*)d_in[0];   // (B,T,I)
  const float* h0 = (const float*)d_in[1];   // (B,D)
  const float* zv = (const float*)d_in[2];   // (I,P,D)
  const float* hv = (const float*)d_in[3];   // (I,P,D)
  const float* ov = (const float*)d_in[4];   // (D,P,O)

  float* y  = (float*)d_out;                     // (B,T,O)
  float* ht = (float*)d_out + (size_t)NT * OO;   // (B,T,D)

  const int smem1 = 64 * SW1 * 4 + 3 * 16384;    // 66048
  const int smem3 = 128 * SW3 * 4 + 3 * 4096;    // 78848
  cudaFuncSetAttribute(k1_mma, cudaFuncAttributeMaxDynamicSharedMemorySize, smem1);
  cudaFuncSetAttribute(k3_mma, cudaFuncAttributeMaxDynamicSharedMemorySize, smem3);

  k0_prep<<<(32*32*32 + 64*8*32 + 255) / 256, 256>>>(zv, hv, ov);
  k1_mma<<<512, 128, smem1>>>(x);
  k2b_scan<<<BB, DD>>>(h0);
  k3_mma<<<256, 128, smem3>>>(ht, y);
}